// round 11
// baseline (speedup 1.0000x reference)
#include <cuda_runtime.h>
#include <cuda_fp16.h>
#include <cstdint>

#define Bb   512
#define NN   24
#define TT   25

// ---------------- scratch (device globals) ----------------
__device__ half  g_xiH[NN*Bb*80],  g_xiL[NN*Bb*80];     // xi padded 72->80
__device__ half  g_h1H[NN*Bb*128], g_h1L[NN*Bb*128];
__device__ half  g_h2H[NN*Bb*128], g_h2L[NN*Bb*128];
__device__ half  g_yiH[NN*Bb*128], g_yiL[NN*Bb*128];
__device__ half  g_encH[NN*Bb*256], g_encL[NN*Bb*256];  // node-major enc halves
__device__ float g_c1[NN*Bb*128], g_c2[NN*Bb*128];
__device__ float g_gates[NN*Bb*512];
__device__ float g_fcpre[NN*Bb*256];                    // also reused as init y
__device__ float g_locstart[Bb*NN*4];

// prepacked weights (hi/lo fp16):
__device__ half g_w0H[NN*208*512], g_w0L[NN*208*512];   // [Wx0(80 pad) ; Wh0(128)]
__device__ half g_w1H[NN*256*512], g_w1L[NN*256*512];   // [Wx1 ; Wh1]
__device__ half g_wfH[NN*128*256], g_wfL[NN*128*256];   // fcW | fc2W
__device__ half g_wiH[256*256],    g_wiL[256*256];      // [ih1W | ih2W] (shared over n)
__device__ float g_fcBc[NN*256];
__device__ float g_ihBc[NN*256];                        // [ih1b | ih2b] replicated

// ---------------- activations ----------------
__device__ __forceinline__ float sigf(float x){ return 1.0f/(1.0f+__expf(-x)); }
__device__ __forceinline__ float tanhacc(float x){
    float ax = fabsf(x);
    float e  = __expf(-2.0f*ax);
    float t  = (1.0f - e)/(1.0f + e);
    return copysignf(t, x);
}
__device__ __forceinline__ void splitH(float x, half& h, half& l){
    h = __float2half_rn(x);
    l = __float2half_rn(x - __half2float(h));
}

// ---------------- mma helpers ----------------
__device__ __forceinline__ uint32_t sptr(const void* p){
    return (uint32_t)__cvta_generic_to_shared(p);
}
__device__ __forceinline__ void ldm4(uint32_t* r, const half* p){
    asm volatile("ldmatrix.sync.aligned.m8n8.x4.shared.b16 {%0,%1,%2,%3},[%4];"
        : "=r"(r[0]),"=r"(r[1]),"=r"(r[2]),"=r"(r[3]) : "r"(sptr(p)));
}
__device__ __forceinline__ void ldm4t(uint32_t* r, const half* p){
    asm volatile("ldmatrix.sync.aligned.m8n8.x4.trans.shared.b16 {%0,%1,%2,%3},[%4];"
        : "=r"(r[0]),"=r"(r[1]),"=r"(r[2]),"=r"(r[3]) : "r"(sptr(p)));
}
__device__ __forceinline__ void mma16(float* c, const uint32_t* a, const uint32_t* b){
    asm volatile(
      "mma.sync.aligned.m16n8k16.row.col.f32.f16.f16.f32 "
      "{%0,%1,%2,%3},{%4,%5,%6,%7},{%8,%9},{%0,%1,%2,%3};"
      : "+f"(c[0]),"+f"(c[1]),"+f"(c[2]),"+f"(c[3])
      : "r"(a[0]),"r"(a[1]),"r"(a[2]),"r"(a[3]),"r"(b[0]),"r"(b[1]));
}

// ---------------------------------------------------------------------------
// Per-node fp16-split GEMM (R3 skeleton + REGISTER PREFETCH; Kw=0 -> shared W):
//   out[(n*Bb+b)*O_w + o] = bias[n*O_w+o] + A1*W[0:16*kc1] (+ A2*W onward)
// grid (NN, O_w/128, Bb/64), 256 thr. Tile 64x128, k-chunk 16.
// 8 warps = 2(M)x4(N); warp 32x32; 3-product hi/lo split.
// ---------------------------------------------------------------------------
#define SAS 24     // A smem row stride in halves (16+8)
#define SWS 136    // W smem row stride in halves (128+8)

__global__ void __launch_bounds__(256) gemm_fp16(
    const half* __restrict__ AH1, const half* __restrict__ AL1, int kc1, int sA1,
    const half* __restrict__ AH2, const half* __restrict__ AL2, int kc2, int sA2,
    const half* __restrict__ WH,  const half* __restrict__ WL,  int Kw,
    const float* __restrict__ bias, int O_w, float* __restrict__ out)
{
    __shared__ half sAh[64*SAS], sAl[64*SAS];
    __shared__ half sWh[16*SWS], sWl[16*SWS];

    const int n  = blockIdx.x;
    const int o0 = blockIdx.y << 7;
    const int b0 = blockIdx.z << 6;
    const int t  = threadIdx.x, lane = t & 31, w = t >> 5;
    const int wM = (w >> 2) << 5;       // 0 / 32
    const int wN = (w & 3)  << 5;       // 0..96
    const int g  = lane >> 2, t4 = lane & 3;

    const int aoff = (lane & 15)*SAS + (lane >> 4)*8;
    const int boff = (lane & 15)*SWS + wN + (lane >> 4)*8;

    const int wrow = t >> 4, wc16 = t & 15;      // W loader
    const int tt = t & 127, arow = tt >> 1, achk = tt & 1;  // A loader

    float acc[2][4][4];
    #pragma unroll
    for (int mt=0;mt<2;mt++)
        #pragma unroll
        for (int nt=0;nt<4;nt++)
            #pragma unroll
            for (int j=0;j<4;j++) acc[mt][nt][j]=0.f;

    const int total = kc1 + kc2;

    // ---- register prefetch state ----
    uint4 rA, rWh, rWl;
    auto loadRegs = [&](int c){
        const half* pA = (c < kc1) ? (t < 128 ? AH1 : AL1) : (t < 128 ? AH2 : AL2);
        const int   sA = (c < kc1) ? sA1 : sA2;
        const int   k0 = (c < kc1) ? c*16 : (c-kc1)*16;
        rA  = *(const uint4*)&pA[((long)n*Bb + b0 + arow)*sA + k0 + achk*8];
        long gw = ((long)n*Kw + c*16 + wrow)*O_w + o0 + wc16*8;
        rWh = *(const uint4*)&WH[gw];
        rWl = *(const uint4*)&WL[gw];
    };

    loadRegs(0);
    #pragma unroll 1
    for (int c=0; c<total; c++){
        __syncthreads();
        // ---- store prefetched regs to smem ----
        {
            half* dst = (t < 128 ? sAh : sAl) + arow*SAS + achk*8;
            *(uint4*)dst = rA;
            *(uint4*)&sWh[wrow*SWS + wc16*8] = rWh;
            *(uint4*)&sWl[wrow*SWS + wc16*8] = rWl;
        }
        __syncthreads();
        // ---- prefetch next chunk (LDG latency overlaps MMAs below) ----
        if (c+1 < total) loadRegs(c+1);
        // ---- fragments ----
        uint32_t ah[2][4], al[2][4];
        #pragma unroll
        for (int mt=0;mt<2;mt++){
            ldm4(ah[mt], &sAh[(wM + mt*16)*SAS + aoff]);
            ldm4(al[mt], &sAl[(wM + mt*16)*SAS + aoff]);
        }
        uint32_t bh[4][2], bl[4][2];
        #pragma unroll
        for (int p=0;p<2;p++){
            uint32_t r[4];
            ldm4t(r, &sWh[boff + p*16]);
            bh[2*p][0]=r[0]; bh[2*p][1]=r[1]; bh[2*p+1][0]=r[2]; bh[2*p+1][1]=r[3];
            ldm4t(r, &sWl[boff + p*16]);
            bl[2*p][0]=r[0]; bl[2*p][1]=r[1]; bl[2*p+1][0]=r[2]; bl[2*p+1][1]=r[3];
        }
        // ---- 3-product split MMAs ----
        #pragma unroll
        for (int nt=0;nt<4;nt++){
            #pragma unroll
            for (int mt=0;mt<2;mt++){
                mma16(acc[mt][nt], ah[mt], bh[nt]);
                mma16(acc[mt][nt], ah[mt], bl[nt]);
                mma16(acc[mt][nt], al[mt], bh[nt]);
            }
        }
    }
    // ---- epilogue: bias + store ----
    #pragma unroll
    for (int mt=0;mt<2;mt++){
        const int r0 = b0 + wM + mt*16 + g;
        #pragma unroll
        for (int nt=0;nt<4;nt++){
            const int oc = o0 + wN + nt*8 + t4*2;
            const float bv0 = bias[n*O_w + oc];
            const float bv1 = bias[n*O_w + oc + 1];
            long base0 = ((long)n*Bb + r0    )*O_w + oc;
            long base1 = ((long)n*Bb + r0 + 8)*O_w + oc;
            *(float2*)&out[base0] = make_float2(acc[mt][nt][0]+bv0, acc[mt][nt][1]+bv1);
            *(float2*)&out[base1] = make_float2(acc[mt][nt][2]+bv0, acc[mt][nt][3]+bv1);
        }
    }
}

// ---------------------------------------------------------------------------
// G-mix + LSTM cell (R3 design). grid (Bb, 4) x 128 threads.
// ---------------------------------------------------------------------------
__global__ void __launch_bounds__(128) lstm_mix(
    const float* __restrict__ gates, const float* __restrict__ G,
    const float* __restrict__ c_in,  float* __restrict__ c_out,
    half* __restrict__ hH, half* __restrict__ hL,
    half* __restrict__ yiH, half* __restrict__ yiL)
{
    __shared__ float sGt[NN*128];   // [n][grp*32 + c]
    __shared__ float sGm[NN*NN];

    const int b = blockIdx.x, c0 = blockIdx.y*32;
    const int t = threadIdx.x;

    for (int i=t; i<NN*4*8; i+=128){
        int f4 = i & 7, grp = (i>>3)&3, n = i>>5;
        float4 v = *(const float4*)&gates[((long)n*Bb + b)*512 + grp*128 + c0 + f4*4];
        *(float4*)&sGt[n*128 + grp*32 + f4*4] = v;
    }
    for (int i=t; i<NN*NN; i+=128) sGm[i] = G[i];
    __syncthreads();

    const int c = t & 31, mg = t >> 5;   // mg: 0..3, each 6 m
    float acc[6][4];
    #pragma unroll
    for (int mm=0;mm<6;mm++)
        #pragma unroll
        for (int j=0;j<4;j++) acc[mm][j]=0.f;

    #pragma unroll 4
    for (int n=0;n<NN;n++){
        float vi = sGt[n*128 +      c];
        float vf = sGt[n*128 + 32 + c];
        float vg = sGt[n*128 + 64 + c];
        float vo = sGt[n*128 + 96 + c];
        #pragma unroll
        for (int mm=0;mm<6;mm++){
            float gm = sGm[(mg*6+mm)*NN + n];
            acc[mm][0] = fmaf(gm, vi, acc[mm][0]);
            acc[mm][1] = fmaf(gm, vf, acc[mm][1]);
            acc[mm][2] = fmaf(gm, vg, acc[mm][2]);
            acc[mm][3] = fmaf(gm, vo, acc[mm][3]);
        }
    }
    #pragma unroll
    for (int mm=0;mm<6;mm++){
        const int m = mg*6+mm;
        const long idx = ((long)m*Bb + b)*128 + c0 + c;
        float cold = c_in[idx];
        float cn = sigf(acc[mm][1])*cold + sigf(acc[mm][0])*tanhacc(acc[mm][2]);
        float hn = sigf(acc[mm][3])*tanhacc(cn);
        c_out[idx] = cn;
        half h,l; splitH(hn, h, l);
        hH[idx]=h; hL[idx]=l;
        if (yiH){
            float y = tanhacc(hn);
            splitH(y, h, l);
            yiH[idx]=h; yiL[idx]=l;
        }
    }
}

// ---------------------------------------------------------------------------
// Head (R3 design)
// ---------------------------------------------------------------------------
__global__ void __launch_bounds__(256) head_kernel(
    const float* __restrict__ G,
    const float* __restrict__ locW, const float* __restrict__ locB,
    const float* __restrict__ lzW,  const float* __restrict__ lzB,
    float* __restrict__ out, int tstep)
{
    extern __shared__ float smem[];
    float* sP  = smem;                 // NN*256
    float* sY  = sP  + NN*256;         // NN*256
    float* sG  = sY  + NN*256;         // NN*NN
    float* sQ  = sG  + NN*NN;          // NN*8
    float* sLW = sQ  + NN*8;           // 384
    float* sLZ = sLW + 128*3;          // 512

    const int b = blockIdx.x, t = threadIdx.x;
    for (int i=t;i<NN*256;i+=256){
        int n = i>>8, f = i&255;
        sP[i] = g_fcpre[((long)n*Bb + b)*256 + f];
    }
    for (int i=t;i<NN*NN;i+=256)  sG[i]=G[i];
    for (int i=t;i<384;i+=256)    sLW[i]=locW[i];
    for (int i=t;i<512;i+=256)    sLZ[i]=lzW[i];
    __syncthreads();

    {
        const int ocg = t & 63;
        const int mg  = t >> 6;
        const float4* p4 = (const float4*)sP;
        float acc[6][4];
        #pragma unroll
        for (int mm=0;mm<6;mm++)
            #pragma unroll
            for (int j=0;j<4;j++) acc[mm][j]=0.f;
        #pragma unroll 4
        for (int n=0;n<NN;n++){
            float4 v = p4[n*64 + ocg];
            #pragma unroll
            for (int mm=0;mm<6;mm++){
                float gm = sG[(mg*6+mm)*NN + n];
                acc[mm][0]=fmaf(gm,v.x,acc[mm][0]); acc[mm][1]=fmaf(gm,v.y,acc[mm][1]);
                acc[mm][2]=fmaf(gm,v.z,acc[mm][2]); acc[mm][3]=fmaf(gm,v.w,acc[mm][3]);
            }
        }
        #pragma unroll
        for (int mm=0;mm<6;mm++){
            int m = mg*6+mm;
            *(float4*)&sY[m*256 + ocg*4] =
                make_float4(tanhacc(acc[mm][0]),tanhacc(acc[mm][1]),
                            tanhacc(acc[mm][2]),tanhacc(acc[mm][3]));
        }
    }
    __syncthreads();

    if (t < NN*7){
        int n = t/7, j = t%7;
        float a;
        if (j < 3){
            a = locB[j];
            #pragma unroll 8
            for (int f=0;f<128;f++) a = fmaf(sY[n*256+f], sLW[f*3+j], a);
        } else {
            int j2 = j-3;
            a = lzB[j2];
            #pragma unroll 8
            for (int f=0;f<128;f++) a = fmaf(sY[n*256+128+f], sLZ[f*4+j2], a);
        }
        sQ[n*8+j] = a;
    }
    __syncthreads();

    if (t < NN){
        int m = t;
        float s[7];
        #pragma unroll
        for (int j=0;j<7;j++){
            float a = 0.f;
            #pragma unroll 4
            for (int n=0;n<NN;n++) a = fmaf(sG[m*NN+n], sQ[n*8+j], a);
            s[j]=a;
        }
        float inv = rsqrtf(1.0f + s[0]*s[0] + s[1]*s[1] + s[2]*s[2]);
        float dw=inv, dx=s[0]*inv, dy=s[1]*inv, dz=s[2]*inv;
        long bm = (long)b*NN + m;
        float qw=g_locstart[bm*4+0], qx=g_locstart[bm*4+1],
              qy=g_locstart[bm*4+2], qz=g_locstart[bm*4+3];
        float lw = qw*dw - qx*dx - qy*dy - qz*dz;
        float lx = qw*dx + qx*dw + qy*dz - qz*dy;
        float ly = qw*dy - qx*dz + qy*dw + qz*dx;
        float lz = qw*dz + qx*dy - qy*dx + qz*dw;
        g_locstart[bm*4+0]=lw; g_locstart[bm*4+1]=lx;
        g_locstart[bm*4+2]=ly; g_locstart[bm*4+3]=lz;

        long oo = (((long)b*TT + tstep)*NN + m)*4;
        out[oo+0]=lw; out[oo+1]=lx; out[oo+2]=ly; out[oo+3]=lz;
        long oz = (long)Bb*TT*NN*4 + oo;
        out[oz+0]=s[3]; out[oz+1]=s[4]; out[oz+2]=s[5]; out[oz+3]=s[6];

        long xb = ((long)m*Bb + b)*80 + 64;
        float xv[8] = {lw,lx,ly,lz,dw,dx,dy,dz};
        #pragma unroll
        for (int j=0;j<8;j++){
            half h,l; splitH(xv[j], h, l);
            g_xiH[xb+j]=h; g_xiL[xb+j]=l;
        }
    }
}

// ---------------------------------------------------------------------------
// init_mix: h0/c0 = G @ y where y = [y1|y2] (from tensor-core init GEMM)
// ---------------------------------------------------------------------------
__global__ void __launch_bounds__(256) init_mix(
    const float* __restrict__ y, const float* __restrict__ G)
{
    __shared__ float sY[NN*256];
    __shared__ float sG[NN*NN];
    const int b = blockIdx.x, t = threadIdx.x;
    for (int i=t;i<NN*256;i+=256){
        int n = i>>8, f = i&255;
        sY[i] = y[((long)n*Bb + b)*256 + f];
    }
    for (int i=t;i<NN*NN;i+=256) sG[i]=G[i];
    __syncthreads();
    for (int idx=t; idx<NN*128; idx+=256){
        int m = idx>>7, o = idx&127;
        float h0=0.f, c0=0.f;
        #pragma unroll 4
        for (int n=0;n<NN;n++){
            float gm = sG[m*NN+n];
            h0 = fmaf(gm, sY[n*256+o],     h0);
            c0 = fmaf(gm, sY[n*256+128+o], c0);
        }
        long off = ((long)m*Bb + b)*128 + o;
        g_c1[off]=c0; g_c2[off]=c0;
        half h,l; splitH(h0, h, l);
        g_h1H[off]=h; g_h1L[off]=l;
        g_h2H[off]=h; g_h2L[off]=l;
    }
}

// ---------------------------------------------------------------------------
// init_xi: xi halves + locstart + enc transpose (b-major -> node-major halves)
// ---------------------------------------------------------------------------
__global__ void init_xi(const float* __restrict__ x, const float* __restrict__ z,
                        const float* __restrict__ enc)
{
    int i = blockIdx.x*blockDim.x + threadIdx.x;
    if (i < NN*Bb*80){
        int f = i % 80, nb = i / 80;
        int b = nb % Bb, n = nb / Bb;
        float v = 0.f;
        if (f < 64)      v = z[(b*NN + n)*64 + f];
        else if (f < 72) v = x[(b*NN + n)*8 + (f-64)];
        half h,l; splitH(v, h, l);
        g_xiH[i]=h; g_xiL[i]=l;
    }
    if (i < Bb*NN*4){
        int j = i % 4, bn = i / 4;
        g_locstart[i] = x[bn*8 + j];
    }
    if (i < NN*Bb*256){
        int f = i % 256, nb = i / 256;
        int b = nb % Bb, n = nb / Bb;
        half h,l; splitH(enc[((long)b*NN + n)*256 + f], h, l);
        g_encH[i]=h; g_encL[i]=l;
    }
}

// ---------------------------------------------------------------------------
// fused prepack: 9 jobs by blockIdx.y
// ---------------------------------------------------------------------------
__global__ void prep_all(
    const float* __restrict__ Wx0, const float* __restrict__ Wh0,
    const float* __restrict__ Wx1, const float* __restrict__ Wh1,
    const float* __restrict__ fcW, const float* __restrict__ fc2W,
    const float* __restrict__ fcB, const float* __restrict__ fc2B,
    const float* __restrict__ ih1W, const float* __restrict__ ih2W,
    const float* __restrict__ ih1B, const float* __restrict__ ih2B)
{
    const int job = blockIdx.y;
    if (job == 6){
        for (int i = blockIdx.x*blockDim.x + threadIdx.x; i < NN*256;
             i += gridDim.x*blockDim.x){
            int n = i >> 8, j = i & 255;
            g_fcBc[i] = (j < 128) ? fcB[n*128 + j] : fc2B[n*128 + (j-128)];
            g_ihBc[i] = (j < 128) ? ih1B[j] : ih2B[j-128];
        }
        return;
    }
    if (job >= 7){
        const float* src = (job == 7) ? ih1W : ih2W;
        const int colOff = (job == 7) ? 0 : 128;
        for (int i = blockIdx.x*blockDim.x + threadIdx.x; i < 256*128;
             i += gridDim.x*blockDim.x){
            int r = i >> 7, o = i & 127;
            half h,l; splitH(src[r*128 + o], h, l);
            int di = r*256 + colOff + o;
            g_wiH[di]=h; g_wiL[di]=l;
        }
        return;
    }
    const float* src; half *dH, *dL;
    int Ksrc, Osrc, Kdst, Odst, rowOff, colOff, rows;
    switch(job){
        case 0: src=Wx0; dH=g_w0H; dL=g_w0L; Ksrc=72;  Osrc=512; Kdst=208; Odst=512; rowOff=0;   colOff=0;   rows=80;  break;
        case 1: src=Wh0; dH=g_w0H; dL=g_w0L; Ksrc=128; Osrc=512; Kdst=208; Odst=512; rowOff=80;  colOff=0;   rows=128; break;
        case 2: src=Wx1; dH=g_w1H; dL=g_w1L; Ksrc=128; Osrc=512; Kdst=256; Odst=512; rowOff=0;   colOff=0;   rows=128; break;
        case 3: src=Wh1; dH=g_w1H; dL=g_w1L; Ksrc=128; Osrc=512; Kdst=256; Odst=512; rowOff=128; colOff=0;   rows=128; break;
        case 4: src=fcW; dH=g_wfH; dL=g_wfL; Ksrc=128; Osrc=128; Kdst=128; Odst=256; rowOff=0;   colOff=0;   rows=128; break;
        default:src=fc2W;dH=g_wfH; dL=g_wfL; Ksrc=128; Osrc=128; Kdst=128; Odst=256; rowOff=0;   colOff=128; rows=128; break;
    }
    long total = (long)NN*rows*Osrc;
    for (long idx = blockIdx.x*blockDim.x + threadIdx.x; idx < total;
         idx += (long)gridDim.x*blockDim.x){
        int o = idx % Osrc;
        int r = (idx / Osrc) % rows;
        int n = idx / ((long)Osrc*rows);
        float v = (r < Ksrc) ? src[((long)n*Ksrc + r)*Osrc + o] : 0.f;
        half h,l; splitH(v, h, l);
        long di = ((long)n*Kdst + rowOff + r)*Odst + colOff + o;
        dH[di]=h; dL[di]=l;
    }
}

// ---------------------------------------------------------------------------
extern "C" void kernel_launch(void* const* d_in, const int* in_sizes, int n_in,
                              void* d_out, int out_size)
{
    const float* x    = (const float*)d_in[0];
    const float* enc  = (const float*)d_in[1];
    const float* z    = (const float*)d_in[2];
    const float* G    = (const float*)d_in[4];
    const float* Wx0  = (const float*)d_in[5];
    const float* Wh0  = (const float*)d_in[6];
    const float* b0_  = (const float*)d_in[7];
    const float* Wx1  = (const float*)d_in[8];
    const float* Wh1  = (const float*)d_in[9];
    const float* b1_  = (const float*)d_in[10];
    const float* fcW  = (const float*)d_in[11];
    const float* fcB  = (const float*)d_in[12];
    const float* fc2W = (const float*)d_in[13];
    const float* fc2B = (const float*)d_in[14];
    const float* ih1W = (const float*)d_in[15];
    const float* ih1B = (const float*)d_in[16];
    const float* ih2W = (const float*)d_in[17];
    const float* ih2B = (const float*)d_in[18];
    const float* locW = (const float*)d_in[19];
    const float* locB = (const float*)d_in[20];
    const float* lzW  = (const float*)d_in[21];
    const float* lzB  = (const float*)d_in[22];
    float* out = (float*)d_out;

    half *xiH,*xiL,*h1H,*h1L,*h2H,*h2L,*yiH,*yiL,*encH,*encL;
    half *w0H,*w0L,*w1H,*w1L,*wfH,*wfL,*wiH,*wiL;
    float *c1,*c2,*gates,*fcpre,*fcBc,*ihBc;
    cudaGetSymbolAddress((void**)&xiH, g_xiH); cudaGetSymbolAddress((void**)&xiL, g_xiL);
    cudaGetSymbolAddress((void**)&h1H, g_h1H); cudaGetSymbolAddress((void**)&h1L, g_h1L);
    cudaGetSymbolAddress((void**)&h2H, g_h2H); cudaGetSymbolAddress((void**)&h2L, g_h2L);
    cudaGetSymbolAddress((void**)&yiH, g_yiH); cudaGetSymbolAddress((void**)&yiL, g_yiL);
    cudaGetSymbolAddress((void**)&encH, g_encH); cudaGetSymbolAddress((void**)&encL, g_encL);
    cudaGetSymbolAddress((void**)&w0H, g_w0H); cudaGetSymbolAddress((void**)&w0L, g_w0L);
    cudaGetSymbolAddress((void**)&w1H, g_w1H); cudaGetSymbolAddress((void**)&w1L, g_w1L);
    cudaGetSymbolAddress((void**)&wfH, g_wfH); cudaGetSymbolAddress((void**)&wfL, g_wfL);
    cudaGetSymbolAddress((void**)&wiH, g_wiH); cudaGetSymbolAddress((void**)&wiL, g_wiL);
    cudaGetSymbolAddress((void**)&c1, g_c1);   cudaGetSymbolAddress((void**)&c2, g_c2);
    cudaGetSymbolAddress((void**)&gates, g_gates);
    cudaGetSymbolAddress((void**)&fcpre, g_fcpre);
    cudaGetSymbolAddress((void**)&fcBc, g_fcBc);
    cudaGetSymbolAddress((void**)&ihBc, g_ihBc);

    const int smem_head = (NN*256 + NN*256 + NN*NN + NN*8 + 128*3 + 128*4)*4;
    cudaFuncSetAttribute(head_kernel,cudaFuncAttributeMaxDynamicSharedMemorySize, smem_head);

    // ---- setup ----
    prep_all<<<dim3(256,9), 256>>>(Wx0, Wh0, Wx1, Wh1, fcW, fc2W, fcB, fc2B,
                                   ih1W, ih2W, ih1B, ih2B);
    init_xi<<<(NN*Bb*256 + 255)/256, 256>>>(x, z, enc);
    // y = enc @ [ih1W|ih2W] + [ih1b|ih2b]   (shared weights: Kw stride = 0)
    gemm_fp16<<<dim3(NN,2,8), 256>>>(encH, encL, 16, 256,
                                     (half*)nullptr, (half*)nullptr, 0, 0,
                                     wiH, wiL, 0, ihBc, 256, fcpre);
    init_mix<<<Bb, 256>>>(fcpre, G);

    dim3 gl(NN, 4, Bb/64);   // lstm gemms: O=512
    dim3 gf(NN, 2, Bb/64);   // fc gemm:   O=256
    dim3 gm(Bb, 4);          // lstm_mix

    for (int t = 0; t < TT; t++){
        gemm_fp16<<<gl, 256>>>(xiH, xiL, 5, 80,  h1H, h1L, 8, 128,
                               w0H, w0L, 208, b0_, 512, gates);
        lstm_mix <<<gm, 128>>>(gates, G, c1, c1, h1H, h1L, nullptr, nullptr);
        gemm_fp16<<<gl, 256>>>(h1H, h1L, 8, 128, h2H, h2L, 8, 128,
                               w1H, w1L, 256, b1_, 512, gates);
        lstm_mix <<<gm, 128>>>(gates, G, c2, c2, h2H, h2L, yiH, yiL);
        gemm_fp16<<<gf, 256>>>(yiH, yiL, 8, 128, (half*)nullptr, (half*)nullptr, 0, 0,
                               wfH, wfL, 128, fcBc, 256, fcpre);
        head_kernel<<<Bb, 256, smem_head>>>(G, locW, locB, lzW, lzB, out, t);
    }
}

// round 13
// speedup vs baseline: 1.0610x; 1.0610x over previous
#include <cuda_runtime.h>
#include <cuda_fp16.h>
#include <cstdint>

#define Bb   512
#define NN   24
#define TT   25

// ---------------- scratch (device globals) ----------------
__device__ half  g_xiH[NN*Bb*96],  g_xiL[NN*Bb*96];     // xi padded 72->96
__device__ half  g_h1H[NN*Bb*128], g_h1L[NN*Bb*128];
__device__ half  g_h2H[NN*Bb*128], g_h2L[NN*Bb*128];
__device__ half  g_yiH[NN*Bb*128], g_yiL[NN*Bb*128];
__device__ half  g_encH[NN*Bb*256], g_encL[NN*Bb*256];  // node-major enc halves
__device__ float g_c1[NN*Bb*128], g_c2[NN*Bb*128];
__device__ float g_gates[NN*Bb*512];
__device__ float g_fcpre[NN*Bb*256];                    // also reused as init y
__device__ float g_locstart[Bb*NN*4];

// prepacked weights (hi/lo fp16):
__device__ half g_w0H[NN*224*512], g_w0L[NN*224*512];   // [Wx0(96 pad) ; Wh0(128)]
__device__ half g_w1H[NN*256*512], g_w1L[NN*256*512];   // [Wx1 ; Wh1]
__device__ half g_wfH[NN*128*256], g_wfL[NN*128*256];   // fcW | fc2W
__device__ half g_wiH[256*256],    g_wiL[256*256];      // [ih1W | ih2W] (shared over n)
__device__ float g_fcBc[NN*256];
__device__ float g_ihBc[NN*256];                        // [ih1b | ih2b] replicated

// ---------------- activations ----------------
__device__ __forceinline__ float sigf(float x){ return 1.0f/(1.0f+__expf(-x)); }
__device__ __forceinline__ float tanhacc(float x){
    float ax = fabsf(x);
    float e  = __expf(-2.0f*ax);
    float t  = (1.0f - e)/(1.0f + e);
    return copysignf(t, x);
}
__device__ __forceinline__ void splitH(float x, half& h, half& l){
    h = __float2half_rn(x);
    l = __float2half_rn(x - __half2float(h));
}

// ---------------- mma helpers ----------------
__device__ __forceinline__ uint32_t sptr(const void* p){
    return (uint32_t)__cvta_generic_to_shared(p);
}
__device__ __forceinline__ void ldm4(uint32_t* r, const half* p){
    asm volatile("ldmatrix.sync.aligned.m8n8.x4.shared.b16 {%0,%1,%2,%3},[%4];"
        : "=r"(r[0]),"=r"(r[1]),"=r"(r[2]),"=r"(r[3]) : "r"(sptr(p)));
}
__device__ __forceinline__ void ldm4t(uint32_t* r, const half* p){
    asm volatile("ldmatrix.sync.aligned.m8n8.x4.trans.shared.b16 {%0,%1,%2,%3},[%4];"
        : "=r"(r[0]),"=r"(r[1]),"=r"(r[2]),"=r"(r[3]) : "r"(sptr(p)));
}
__device__ __forceinline__ void mma16(float* c, const uint32_t* a, const uint32_t* b){
    asm volatile(
      "mma.sync.aligned.m16n8k16.row.col.f32.f16.f16.f32 "
      "{%0,%1,%2,%3},{%4,%5,%6,%7},{%8,%9},{%0,%1,%2,%3};"
      : "+f"(c[0]),"+f"(c[1]),"+f"(c[2]),"+f"(c[3])
      : "r"(a[0]),"r"(a[1]),"r"(a[2]),"r"(a[3]),"r"(b[0]),"r"(b[1]));
}

// ---------------------------------------------------------------------------
// Per-node fp16-split GEMM, k-chunk 32 (halved barrier count vs R3).
//   out[(n*Bb+b)*O_w + o] = bias[n*O_w+o] + A1*W[0:32*kc1] (+ A2*W onward)
// grid (NN, O_w/128, Bb/64), 256 thr. Tile 64x128.
// 8 warps = 2(M)x4(N); warp 32x32; 3-product hi/lo split.  Kw=0 -> shared W.
// ---------------------------------------------------------------------------
#define SAS 40     // A smem row stride in halves (32+8)
#define SWS 136    // W smem row stride in halves (128+8)

__global__ void __launch_bounds__(256) gemm_fp16(
    const half* __restrict__ AH1, const half* __restrict__ AL1, int kc1, int sA1,
    const half* __restrict__ AH2, const half* __restrict__ AL2, int kc2, int sA2,
    const half* __restrict__ WH,  const half* __restrict__ WL,  int Kw,
    const float* __restrict__ bias, int O_w, float* __restrict__ out)
{
    __shared__ half sAh[64*SAS], sAl[64*SAS];
    __shared__ half sWh[32*SWS], sWl[32*SWS];

    const int n  = blockIdx.x;
    const int o0 = blockIdx.y << 7;
    const int b0 = blockIdx.z << 6;
    const int t  = threadIdx.x, lane = t & 31, w = t >> 5;
    const int wM = (w >> 2) << 5;       // 0 / 32
    const int wN = (w & 3)  << 5;       // 0..96
    const int g  = lane >> 2, t4 = lane & 3;

    const int aoff = (lane & 15)*SAS + (lane >> 4)*8;
    const int boff = (lane & 15)*SWS + wN + (lane >> 4)*8;

    const int wc16 = t & 15;                 // W loader col (uint4)
    const int wr0  = t >> 4;                 // W loader rows wr0, wr0+16
    const int tt = t & 127;                  // A loader (hi: t<128, lo: t>=128)

    float acc[2][4][4];
    #pragma unroll
    for (int mt=0;mt<2;mt++)
        #pragma unroll
        for (int nt=0;nt<4;nt++)
            #pragma unroll
            for (int j=0;j<4;j++) acc[mt][nt][j]=0.f;

    const int total = kc1 + kc2;
    #pragma unroll 1
    for (int c=0; c<total; c++){
        const half* pA = (c < kc1) ? (t < 128 ? AH1 : AL1) : (t < 128 ? AH2 : AL2);
        const int   sA = (c < kc1) ? sA1 : sA2;
        const int   k0 = (c < kc1) ? c*32 : (c-kc1)*32;
        __syncthreads();
        // ---- stage A (64 x 32 halves, hi & lo): 2 uint4 per thread ----
        {
            half* dst = (t < 128 ? sAh : sAl);
            #pragma unroll
            for (int it=0; it<2; it++){
                int i = tt + it*128;          // 0..255
                int row = i >> 2, chk = i & 3;
                *(uint4*)&dst[row*SAS + chk*8] =
                    *(const uint4*)&pA[((long)n*Bb + b0 + row)*sA + k0 + chk*8];
            }
        }
        // ---- stage W (32 x 128 halves, hi & lo): 2 rows per thread ----
        {
            #pragma unroll
            for (int it=0; it<2; it++){
                int wr = wr0 + it*16;
                long gi = ((long)n*Kw + c*32 + wr)*O_w + o0 + wc16*8;
                *(uint4*)&sWh[wr*SWS + wc16*8] = *(const uint4*)&WH[gi];
                *(uint4*)&sWl[wr*SWS + wc16*8] = *(const uint4*)&WL[gi];
            }
        }
        __syncthreads();
        // ---- compute: 2 k-sub-chunks of 16 ----
        #pragma unroll
        for (int ks=0; ks<2; ks++){
            uint32_t ah[2][4], al[2][4];
            #pragma unroll
            for (int mt=0;mt<2;mt++){
                ldm4(ah[mt], &sAh[(wM + mt*16)*SAS + ks*16 + aoff]);
                ldm4(al[mt], &sAl[(wM + mt*16)*SAS + ks*16 + aoff]);
            }
            uint32_t bh[4][2], bl[4][2];
            #pragma unroll
            for (int p=0;p<2;p++){
                uint32_t r[4];
                ldm4t(r, &sWh[ks*16*SWS + boff + p*16]);
                bh[2*p][0]=r[0]; bh[2*p][1]=r[1]; bh[2*p+1][0]=r[2]; bh[2*p+1][1]=r[3];
                ldm4t(r, &sWl[ks*16*SWS + boff + p*16]);
                bl[2*p][0]=r[0]; bl[2*p][1]=r[1]; bl[2*p+1][0]=r[2]; bl[2*p+1][1]=r[3];
            }
            #pragma unroll
            for (int nt=0;nt<4;nt++){
                #pragma unroll
                for (int mt=0;mt<2;mt++){
                    mma16(acc[mt][nt], ah[mt], bh[nt]);
                    mma16(acc[mt][nt], ah[mt], bl[nt]);
                    mma16(acc[mt][nt], al[mt], bh[nt]);
                }
            }
        }
    }
    // ---- epilogue: bias + store ----
    #pragma unroll
    for (int mt=0;mt<2;mt++){
        const int r0 = b0 + wM + mt*16 + g;
        #pragma unroll
        for (int nt=0;nt<4;nt++){
            const int oc = o0 + wN + nt*8 + t4*2;
            const float bv0 = bias[n*O_w + oc];
            const float bv1 = bias[n*O_w + oc + 1];
            long base0 = ((long)n*Bb + r0    )*O_w + oc;
            long base1 = ((long)n*Bb + r0 + 8)*O_w + oc;
            *(float2*)&out[base0] = make_float2(acc[mt][nt][0]+bv0, acc[mt][nt][1]+bv1);
            *(float2*)&out[base1] = make_float2(acc[mt][nt][2]+bv0, acc[mt][nt][3]+bv1);
        }
    }
}

// ---------------------------------------------------------------------------
// G-mix + LSTM cell (R3 design). grid (Bb, 4) x 128 threads.
// ---------------------------------------------------------------------------
__global__ void __launch_bounds__(128) lstm_mix(
    const float* __restrict__ gates, const float* __restrict__ G,
    const float* __restrict__ c_in,  float* __restrict__ c_out,
    half* __restrict__ hH, half* __restrict__ hL,
    half* __restrict__ yiH, half* __restrict__ yiL)
{
    __shared__ float sGt[NN*128];   // [n][grp*32 + c]
    __shared__ float sGm[NN*NN];

    const int b = blockIdx.x, c0 = blockIdx.y*32;
    const int t = threadIdx.x;

    for (int i=t; i<NN*4*8; i+=128){
        int f4 = i & 7, grp = (i>>3)&3, n = i>>5;
        float4 v = *(const float4*)&gates[((long)n*Bb + b)*512 + grp*128 + c0 + f4*4];
        *(float4*)&sGt[n*128 + grp*32 + f4*4] = v;
    }
    for (int i=t; i<NN*NN; i+=128) sGm[i] = G[i];
    __syncthreads();

    const int c = t & 31, mg = t >> 5;   // mg: 0..3, each 6 m
    float acc[6][4];
    #pragma unroll
    for (int mm=0;mm<6;mm++)
        #pragma unroll
        for (int j=0;j<4;j++) acc[mm][j]=0.f;

    #pragma unroll 4
    for (int n=0;n<NN;n++){
        float vi = sGt[n*128 +      c];
        float vf = sGt[n*128 + 32 + c];
        float vg = sGt[n*128 + 64 + c];
        float vo = sGt[n*128 + 96 + c];
        #pragma unroll
        for (int mm=0;mm<6;mm++){
            float gm = sGm[(mg*6+mm)*NN + n];
            acc[mm][0] = fmaf(gm, vi, acc[mm][0]);
            acc[mm][1] = fmaf(gm, vf, acc[mm][1]);
            acc[mm][2] = fmaf(gm, vg, acc[mm][2]);
            acc[mm][3] = fmaf(gm, vo, acc[mm][3]);
        }
    }
    #pragma unroll
    for (int mm=0;mm<6;mm++){
        const int m = mg*6+mm;
        const long idx = ((long)m*Bb + b)*128 + c0 + c;
        float cold = c_in[idx];
        float cn = sigf(acc[mm][1])*cold + sigf(acc[mm][0])*tanhacc(acc[mm][2]);
        float hn = sigf(acc[mm][3])*tanhacc(cn);
        c_out[idx] = cn;
        half h,l; splitH(hn, h, l);
        hH[idx]=h; hL[idx]=l;
        if (yiH){
            float y = tanhacc(hn);
            splitH(y, h, l);
            yiH[idx]=h; yiL[idx]=l;
        }
    }
}

// ---------------------------------------------------------------------------
// Head (R3 design)
// ---------------------------------------------------------------------------
__global__ void __launch_bounds__(256) head_kernel(
    const float* __restrict__ G,
    const float* __restrict__ locW, const float* __restrict__ locB,
    const float* __restrict__ lzW,  const float* __restrict__ lzB,
    float* __restrict__ out, int tstep)
{
    extern __shared__ float smem[];
    float* sP  = smem;                 // NN*256
    float* sY  = sP  + NN*256;         // NN*256
    float* sG  = sY  + NN*256;         // NN*NN
    float* sQ  = sG  + NN*NN;          // NN*8
    float* sLW = sQ  + NN*8;           // 384
    float* sLZ = sLW + 128*3;          // 512

    const int b = blockIdx.x, t = threadIdx.x;
    for (int i=t;i<NN*256;i+=256){
        int n = i>>8, f = i&255;
        sP[i] = g_fcpre[((long)n*Bb + b)*256 + f];
    }
    for (int i=t;i<NN*NN;i+=256)  sG[i]=G[i];
    for (int i=t;i<384;i+=256)    sLW[i]=locW[i];
    for (int i=t;i<512;i+=256)    sLZ[i]=lzW[i];
    __syncthreads();

    {
        const int ocg = t & 63;
        const int mg  = t >> 6;
        const float4* p4 = (const float4*)sP;
        float acc[6][4];
        #pragma unroll
        for (int mm=0;mm<6;mm++)
            #pragma unroll
            for (int j=0;j<4;j++) acc[mm][j]=0.f;
        #pragma unroll 4
        for (int n=0;n<NN;n++){
            float4 v = p4[n*64 + ocg];
            #pragma unroll
            for (int mm=0;mm<6;mm++){
                float gm = sG[(mg*6+mm)*NN + n];
                acc[mm][0]=fmaf(gm,v.x,acc[mm][0]); acc[mm][1]=fmaf(gm,v.y,acc[mm][1]);
                acc[mm][2]=fmaf(gm,v.z,acc[mm][2]); acc[mm][3]=fmaf(gm,v.w,acc[mm][3]);
            }
        }
        #pragma unroll
        for (int mm=0;mm<6;mm++){
            int m = mg*6+mm;
            *(float4*)&sY[m*256 + ocg*4] =
                make_float4(tanhacc(acc[mm][0]),tanhacc(acc[mm][1]),
                            tanhacc(acc[mm][2]),tanhacc(acc[mm][3]));
        }
    }
    __syncthreads();

    if (t < NN*7){
        int n = t/7, j = t%7;
        float a;
        if (j < 3){
            a = locB[j];
            #pragma unroll 8
            for (int f=0;f<128;f++) a = fmaf(sY[n*256+f], sLW[f*3+j], a);
        } else {
            int j2 = j-3;
            a = lzB[j2];
            #pragma unroll 8
            for (int f=0;f<128;f++) a = fmaf(sY[n*256+128+f], sLZ[f*4+j2], a);
        }
        sQ[n*8+j] = a;
    }
    __syncthreads();

    if (t < NN){
        int m = t;
        float s[7];
        #pragma unroll
        for (int j=0;j<7;j++){
            float a = 0.f;
            #pragma unroll 4
            for (int n=0;n<NN;n++) a = fmaf(sG[m*NN+n], sQ[n*8+j], a);
            s[j]=a;
        }
        float inv = rsqrtf(1.0f + s[0]*s[0] + s[1]*s[1] + s[2]*s[2]);
        float dw=inv, dx=s[0]*inv, dy=s[1]*inv, dz=s[2]*inv;
        long bm = (long)b*NN + m;
        float qw=g_locstart[bm*4+0], qx=g_locstart[bm*4+1],
              qy=g_locstart[bm*4+2], qz=g_locstart[bm*4+3];
        float lw = qw*dw - qx*dx - qy*dy - qz*dz;
        float lx = qw*dx + qx*dw + qy*dz - qz*dy;
        float ly = qw*dy - qx*dz + qy*dw + qz*dx;
        float lz = qw*dz + qx*dy - qy*dx + qz*dw;
        g_locstart[bm*4+0]=lw; g_locstart[bm*4+1]=lx;
        g_locstart[bm*4+2]=ly; g_locstart[bm*4+3]=lz;

        long oo = (((long)b*TT + tstep)*NN + m)*4;
        out[oo+0]=lw; out[oo+1]=lx; out[oo+2]=ly; out[oo+3]=lz;
        long oz = (long)Bb*TT*NN*4 + oo;
        out[oz+0]=s[3]; out[oz+1]=s[4]; out[oz+2]=s[5]; out[oz+3]=s[6];

        long xb = ((long)m*Bb + b)*96 + 64;
        float xv[8] = {lw,lx,ly,lz,dw,dx,dy,dz};
        #pragma unroll
        for (int j=0;j<8;j++){
            half h,l; splitH(xv[j], h, l);
            g_xiH[xb+j]=h; g_xiL[xb+j]=l;
        }
    }
}

// ---------------------------------------------------------------------------
// init_mix: h0/c0 = G @ y where y = [y1|y2] (from tensor-core init GEMM)
// ---------------------------------------------------------------------------
__global__ void __launch_bounds__(256) init_mix(
    const float* __restrict__ y, const float* __restrict__ G)
{
    __shared__ float sY[NN*256];
    __shared__ float sG[NN*NN];
    const int b = blockIdx.x, t = threadIdx.x;
    for (int i=t;i<NN*256;i+=256){
        int n = i>>8, f = i&255;
        sY[i] = y[((long)n*Bb + b)*256 + f];
    }
    for (int i=t;i<NN*NN;i+=256) sG[i]=G[i];
    __syncthreads();
    for (int idx=t; idx<NN*128; idx+=256){
        int m = idx>>7, o = idx&127;
        float h0=0.f, c0=0.f;
        #pragma unroll 4
        for (int n=0;n<NN;n++){
            float gm = sG[m*NN+n];
            h0 = fmaf(gm, sY[n*256+o],     h0);
            c0 = fmaf(gm, sY[n*256+128+o], c0);
        }
        long off = ((long)m*Bb + b)*128 + o;
        g_c1[off]=c0; g_c2[off]=c0;
        half h,l; splitH(h0, h, l);
        g_h1H[off]=h; g_h1L[off]=l;
        g_h2H[off]=h; g_h2L[off]=l;
    }
}

// ---------------------------------------------------------------------------
// init_xi: xi halves + locstart + enc transpose (b-major -> node-major halves)
// ---------------------------------------------------------------------------
__global__ void init_xi(const float* __restrict__ x, const float* __restrict__ z,
                        const float* __restrict__ enc)
{
    int i = blockIdx.x*blockDim.x + threadIdx.x;
    if (i < NN*Bb*96){
        int f = i % 96, nb = i / 96;
        int b = nb % Bb, n = nb / Bb;
        float v = 0.f;
        if (f < 64)      v = z[(b*NN + n)*64 + f];
        else if (f < 72) v = x[(b*NN + n)*8 + (f-64)];
        half h,l; splitH(v, h, l);
        g_xiH[i]=h; g_xiL[i]=l;
    }
    if (i < Bb*NN*4){
        int j = i % 4, bn = i / 4;
        g_locstart[i] = x[bn*8 + j];
    }
    if (i < NN*Bb*256){
        int f = i % 256, nb = i / 256;
        int b = nb % Bb, n = nb / Bb;
        half h,l; splitH(enc[((long)b*NN + n)*256 + f], h, l);
        g_encH[i]=h; g_encL[i]=l;
    }
}

// ---------------------------------------------------------------------------
// fused prepack: 9 jobs by blockIdx.y
// ---------------------------------------------------------------------------
__global__ void prep_all(
    const float* __restrict__ Wx0, const float* __restrict__ Wh0,
    const float* __restrict__ Wx1, const float* __restrict__ Wh1,
    const float* __restrict__ fcW, const float* __restrict__ fc2W,
    const float* __restrict__ fcB, const float* __restrict__ fc2B,
    const float* __restrict__ ih1W, const float* __restrict__ ih2W,
    const float* __restrict__ ih1B, const float* __restrict__ ih2B)
{
    const int job = blockIdx.y;
    if (job == 6){
        for (int i = blockIdx.x*blockDim.x + threadIdx.x; i < NN*256;
             i += gridDim.x*blockDim.x){
            int n = i >> 8, j = i & 255;
            g_fcBc[i] = (j < 128) ? fcB[n*128 + j] : fc2B[n*128 + (j-128)];
            g_ihBc[i] = (j < 128) ? ih1B[j] : ih2B[j-128];
        }
        return;
    }
    if (job >= 7){
        const float* src = (job == 7) ? ih1W : ih2W;
        const int colOff = (job == 7) ? 0 : 128;
        for (int i = blockIdx.x*blockDim.x + threadIdx.x; i < 256*128;
             i += gridDim.x*blockDim.x){
            int r = i >> 7, o = i & 127;
            half h,l; splitH(src[r*128 + o], h, l);
            int di = r*256 + colOff + o;
            g_wiH[di]=h; g_wiL[di]=l;
        }
        return;
    }
    const float* src; half *dH, *dL;
    int Ksrc, Osrc, Kdst, Odst, rowOff, colOff, rows;
    switch(job){
        case 0: src=Wx0; dH=g_w0H; dL=g_w0L; Ksrc=72;  Osrc=512; Kdst=224; Odst=512; rowOff=0;   colOff=0;   rows=96;  break;
        case 1: src=Wh0; dH=g_w0H; dL=g_w0L; Ksrc=128; Osrc=512; Kdst=224; Odst=512; rowOff=96;  colOff=0;   rows=128; break;
        case 2: src=Wx1; dH=g_w1H; dL=g_w1L; Ksrc=128; Osrc=512; Kdst=256; Odst=512; rowOff=0;   colOff=0;   rows=128; break;
        case 3: src=Wh1; dH=g_w1H; dL=g_w1L; Ksrc=128; Osrc=512; Kdst=256; Odst=512; rowOff=128; colOff=0;   rows=128; break;
        case 4: src=fcW; dH=g_wfH; dL=g_wfL; Ksrc=128; Osrc=128; Kdst=128; Odst=256; rowOff=0;   colOff=0;   rows=128; break;
        default:src=fc2W;dH=g_wfH; dL=g_wfL; Ksrc=128; Osrc=128; Kdst=128; Odst=256; rowOff=0;   colOff=128; rows=128; break;
    }
    long total = (long)NN*rows*Osrc;
    for (long idx = blockIdx.x*blockDim.x + threadIdx.x; idx < total;
         idx += (long)gridDim.x*blockDim.x){
        int o = idx % Osrc;
        int r = (idx / Osrc) % rows;
        int n = idx / ((long)Osrc*rows);
        float v = (r < Ksrc) ? src[((long)n*Ksrc + r)*Osrc + o] : 0.f;
        half h,l; splitH(v, h, l);
        long di = ((long)n*Kdst + rowOff + r)*Odst + colOff + o;
        dH[di]=h; dL[di]=l;
    }
}

// ---------------------------------------------------------------------------
extern "C" void kernel_launch(void* const* d_in, const int* in_sizes, int n_in,
                              void* d_out, int out_size)
{
    const float* x    = (const float*)d_in[0];
    const float* enc  = (const float*)d_in[1];
    const float* z    = (const float*)d_in[2];
    const float* G    = (const float*)d_in[4];
    const float* Wx0  = (const float*)d_in[5];
    const float* Wh0  = (const float*)d_in[6];
    const float* b0_  = (const float*)d_in[7];
    const float* Wx1  = (const float*)d_in[8];
    const float* Wh1  = (const float*)d_in[9];
    const float* b1_  = (const float*)d_in[10];
    const float* fcW  = (const float*)d_in[11];
    const float* fcB  = (const float*)d_in[12];
    const float* fc2W = (const float*)d_in[13];
    const float* fc2B = (const float*)d_in[14];
    const float* ih1W = (const float*)d_in[15];
    const float* ih1B = (const float*)d_in[16];
    const float* ih2W = (const float*)d_in[17];
    const float* ih2B = (const float*)d_in[18];
    const float* locW = (const float*)d_in[19];
    const float* locB = (const float*)d_in[20];
    const float* lzW  = (const float*)d_in[21];
    const float* lzB  = (const float*)d_in[22];
    float* out = (float*)d_out;

    half *xiH,*xiL,*h1H,*h1L,*h2H,*h2L,*yiH,*yiL,*encH,*encL;
    half *w0H,*w0L,*w1H,*w1L,*wfH,*wfL,*wiH,*wiL;
    float *c1,*c2,*gates,*fcpre,*fcBc,*ihBc;
    cudaGetSymbolAddress((void**)&xiH, g_xiH); cudaGetSymbolAddress((void**)&xiL, g_xiL);
    cudaGetSymbolAddress((void**)&h1H, g_h1H); cudaGetSymbolAddress((void**)&h1L, g_h1L);
    cudaGetSymbolAddress((void**)&h2H, g_h2H); cudaGetSymbolAddress((void**)&h2L, g_h2L);
    cudaGetSymbolAddress((void**)&yiH, g_yiH); cudaGetSymbolAddress((void**)&yiL, g_yiL);
    cudaGetSymbolAddress((void**)&encH, g_encH); cudaGetSymbolAddress((void**)&encL, g_encL);
    cudaGetSymbolAddress((void**)&w0H, g_w0H); cudaGetSymbolAddress((void**)&w0L, g_w0L);
    cudaGetSymbolAddress((void**)&w1H, g_w1H); cudaGetSymbolAddress((void**)&w1L, g_w1L);
    cudaGetSymbolAddress((void**)&wfH, g_wfH); cudaGetSymbolAddress((void**)&wfL, g_wfL);
    cudaGetSymbolAddress((void**)&wiH, g_wiH); cudaGetSymbolAddress((void**)&wiL, g_wiL);
    cudaGetSymbolAddress((void**)&c1, g_c1);   cudaGetSymbolAddress((void**)&c2, g_c2);
    cudaGetSymbolAddress((void**)&gates, g_gates);
    cudaGetSymbolAddress((void**)&fcpre, g_fcpre);
    cudaGetSymbolAddress((void**)&fcBc, g_fcBc);
    cudaGetSymbolAddress((void**)&ihBc, g_ihBc);

    const int smem_head = (NN*256 + NN*256 + NN*NN + NN*8 + 128*3 + 128*4)*4;
    cudaFuncSetAttribute(head_kernel,cudaFuncAttributeMaxDynamicSharedMemorySize, smem_head);

    // ---- setup ----
    prep_all<<<dim3(256,9), 256>>>(Wx0, Wh0, Wx1, Wh1, fcW, fc2W, fcB, fc2B,
                                   ih1W, ih2W, ih1B, ih2B);
    init_xi<<<(NN*Bb*256 + 255)/256, 256>>>(x, z, enc);
    // y = enc @ [ih1W|ih2W] + [ih1b|ih2b]   (shared weights: Kw stride = 0)
    gemm_fp16<<<dim3(NN,2,8), 256>>>(encH, encL, 8, 256,
                                     (half*)nullptr, (half*)nullptr, 0, 0,
                                     wiH, wiL, 0, ihBc, 256, fcpre);
    init_mix<<<Bb, 256>>>(fcpre, G);

    dim3 gl(NN, 4, Bb/64);   // lstm gemms: O=512
    dim3 gf(NN, 2, Bb/64);   // fc gemm:   O=256
    dim3 gm(Bb, 4);          // lstm_mix

    for (int t = 0; t < TT; t++){
        gemm_fp16<<<gl, 256>>>(xiH, xiL, 3, 96,  h1H, h1L, 4, 128,
                               w0H, w0L, 224, b0_, 512, gates);
        lstm_mix <<<gm, 128>>>(gates, G, c1, c1, h1H, h1L, nullptr, nullptr);
        gemm_fp16<<<gl, 256>>>(h1H, h1L, 4, 128, h2H, h2L, 4, 128,
                               w1H, w1L, 256, b1_, 512, gates);
        lstm_mix <<<gm, 128>>>(gates, G, c2, c2, h2H, h2L, yiH, yiL);
        gemm_fp16<<<gf, 256>>>(yiH, yiL, 4, 128, (half*)nullptr, (half*)nullptr, 0, 0,
                               wfH, wfL, 128, fcBc, 256, fcpre);
        head_kernel<<<Bb, 256, smem_head>>>(G, locW, locB, lzW, lzB, out, t);
    }
}

// round 15
// speedup vs baseline: 1.0747x; 1.0130x over previous
#include <cuda_runtime.h>
#include <cuda_fp16.h>
#include <cstdint>

#define Bb   512
#define NN   24
#define TT   25

// ---------------- scratch (device globals) ----------------
__device__ half  g_xiH[NN*Bb*96],  g_xiL[NN*Bb*96];     // xi padded 72->96
__device__ half  g_h1H[NN*Bb*128], g_h1L[NN*Bb*128];
__device__ half  g_h2H[NN*Bb*128], g_h2L[NN*Bb*128];
__device__ half  g_yiH[NN*Bb*128], g_yiL[NN*Bb*128];
__device__ half  g_encH[NN*Bb*256], g_encL[NN*Bb*256];
__device__ float g_c1[NN*Bb*128], g_c2[NN*Bb*128];
// gates: [(b*4 + cb)*NN + n]*128 + grp*32 + cc   (cb = channel-block 0..3)
__device__ float g_gates[NN*Bb*512];
// fcpre: [(b*NN + n)*256 + f]
__device__ float g_fcpre[NN*Bb*256];
__device__ float g_locstart[Bb*NN*4];

// prepacked weights (hi/lo fp16), [n,K,O] layout:
__device__ half g_w0H[NN*224*512], g_w0L[NN*224*512];   // [Wx0(96 pad) ; Wh0(128)]
__device__ half g_w1H[NN*256*512], g_w1L[NN*256*512];   // [Wx1 ; Wh1]
__device__ half g_wfH[NN*128*256], g_wfL[NN*128*256];   // fcW | fc2W
__device__ half g_wiH[256*256],    g_wiL[256*256];      // [ih1W | ih2W] shared over n
__device__ float g_fcBc[NN*256];
__device__ float g_ihBc[NN*256];

// ---------------- activations ----------------
__device__ __forceinline__ float sigf(float x){ return 1.0f/(1.0f+__expf(-x)); }
__device__ __forceinline__ float tanhacc(float x){
    float ax = fabsf(x);
    float e  = __expf(-2.0f*ax);
    float t  = (1.0f - e)/(1.0f + e);
    return copysignf(t, x);
}
__device__ __forceinline__ void splitH(float x, half& h, half& l){
    h = __float2half_rn(x);
    l = __float2half_rn(x - __half2float(h));
}

// ---------------- mma helpers ----------------
__device__ __forceinline__ uint32_t sptr(const void* p){
    return (uint32_t)__cvta_generic_to_shared(p);
}
__device__ __forceinline__ void ldm4(uint32_t* r, const half* p){
    asm volatile("ldmatrix.sync.aligned.m8n8.x4.shared.b16 {%0,%1,%2,%3},[%4];"
        : "=r"(r[0]),"=r"(r[1]),"=r"(r[2]),"=r"(r[3]) : "r"(sptr(p)));
}
__device__ __forceinline__ void ldm4t(uint32_t* r, const half* p){
    asm volatile("ldmatrix.sync.aligned.m8n8.x4.trans.shared.b16 {%0,%1,%2,%3},[%4];"
        : "=r"(r[0]),"=r"(r[1]),"=r"(r[2]),"=r"(r[3]) : "r"(sptr(p)));
}
__device__ __forceinline__ void mma16(float* c, const uint32_t* a, const uint32_t* b){
    asm volatile(
      "mma.sync.aligned.m16n8k16.row.col.f32.f16.f16.f32 "
      "{%0,%1,%2,%3},{%4,%5,%6,%7},{%8,%9},{%0,%1,%2,%3};"
      : "+f"(c[0]),"+f"(c[1]),"+f"(c[2]),"+f"(c[3])
      : "r"(a[0]),"r"(a[1]),"r"(a[2]),"r"(a[3]),"r"(b[0]),"r"(b[1]));
}

// ---------------------------------------------------------------------------
// Per-node fp16-split GEMM, k-chunk 32.  omode selects output layout:
//   omode 0: gates layout [(r*4+cb)*NN + n]*128 + grp*32 + cc  (O_w=512)
//   omode 1: b-major      [(r*NN + n)*O_w + oc]
// grid (NN, O_w/128, Bb/64), 256 thr. Tile 64x128.
// 8 warps = 2(M)x4(N); warp 32x32; 3-product hi/lo split.  Kw=0 -> shared W.
// ---------------------------------------------------------------------------
#define SAS 40     // A smem row stride in halves (32+8)
#define SWS 136    // W smem row stride in halves (128+8)

__global__ void __launch_bounds__(256) gemm_fp16(
    const half* __restrict__ AH1, const half* __restrict__ AL1, int kc1, int sA1,
    const half* __restrict__ AH2, const half* __restrict__ AL2, int kc2, int sA2,
    const half* __restrict__ WH,  const half* __restrict__ WL,  int Kw,
    const float* __restrict__ bias, int O_w, int omode, float* __restrict__ out)
{
    __shared__ half sAh[64*SAS], sAl[64*SAS];
    __shared__ half sWh[32*SWS], sWl[32*SWS];

    const int n  = blockIdx.x;
    const int o0 = blockIdx.y << 7;
    const int b0 = blockIdx.z << 6;
    const int t  = threadIdx.x, lane = t & 31, w = t >> 5;
    const int wM = (w >> 2) << 5;       // 0 / 32
    const int wN = (w & 3)  << 5;       // 0..96
    const int g  = lane >> 2, t4 = lane & 3;

    const int aoff = (lane & 15)*SAS + (lane >> 4)*8;
    const int boff = (lane & 15)*SWS + wN + (lane >> 4)*8;

    const int wc16 = t & 15;                 // W loader col (uint4)
    const int wr0  = t >> 4;                 // W loader rows wr0, wr0+16
    const int tt = t & 127;                  // A loader (hi: t<128, lo: t>=128)

    float acc[2][4][4];
    #pragma unroll
    for (int mt=0;mt<2;mt++)
        #pragma unroll
        for (int nt=0;nt<4;nt++)
            #pragma unroll
            for (int j=0;j<4;j++) acc[mt][nt][j]=0.f;

    const int total = kc1 + kc2;
    #pragma unroll 1
    for (int c=0; c<total; c++){
        const half* pA = (c < kc1) ? (t < 128 ? AH1 : AL1) : (t < 128 ? AH2 : AL2);
        const int   sA = (c < kc1) ? sA1 : sA2;
        const int   k0 = (c < kc1) ? c*32 : (c-kc1)*32;
        __syncthreads();
        // ---- stage A (64 x 32 halves, hi & lo): 2 uint4 per thread ----
        {
            half* dst = (t < 128 ? sAh : sAl);
            #pragma unroll
            for (int it=0; it<2; it++){
                int i = tt + it*128;
                int row = i >> 2, chk = i & 3;
                *(uint4*)&dst[row*SAS + chk*8] =
                    *(const uint4*)&pA[((long)n*Bb + b0 + row)*sA + k0 + chk*8];
            }
        }
        // ---- stage W (32 x 128 halves, hi & lo): 2 rows per thread ----
        {
            #pragma unroll
            for (int it=0; it<2; it++){
                int wr = wr0 + it*16;
                long gi = ((long)n*Kw + c*32 + wr)*O_w + o0 + wc16*8;
                *(uint4*)&sWh[wr*SWS + wc16*8] = *(const uint4*)&WH[gi];
                *(uint4*)&sWl[wr*SWS + wc16*8] = *(const uint4*)&WL[gi];
            }
        }
        __syncthreads();
        // ---- compute: 2 k-sub-chunks of 16 ----
        #pragma unroll
        for (int ks=0; ks<2; ks++){
            uint32_t ah[2][4], al[2][4];
            #pragma unroll
            for (int mt=0;mt<2;mt++){
                ldm4(ah[mt], &sAh[(wM + mt*16)*SAS + ks*16 + aoff]);
                ldm4(al[mt], &sAl[(wM + mt*16)*SAS + ks*16 + aoff]);
            }
            uint32_t bh[4][2], bl[4][2];
            #pragma unroll
            for (int p=0;p<2;p++){
                uint32_t r[4];
                ldm4t(r, &sWh[ks*16*SWS + boff + p*16]);
                bh[2*p][0]=r[0]; bh[2*p][1]=r[1]; bh[2*p+1][0]=r[2]; bh[2*p+1][1]=r[3];
                ldm4t(r, &sWl[ks*16*SWS + boff + p*16]);
                bl[2*p][0]=r[0]; bl[2*p][1]=r[1]; bl[2*p+1][0]=r[2]; bl[2*p+1][1]=r[3];
            }
            #pragma unroll
            for (int nt=0;nt<4;nt++){
                #pragma unroll
                for (int mt=0;mt<2;mt++){
                    mma16(acc[mt][nt], ah[mt], bh[nt]);
                    mma16(acc[mt][nt], ah[mt], bl[nt]);
                    mma16(acc[mt][nt], al[mt], bh[nt]);
                }
            }
        }
    }
    // ---- epilogue: bias + store (layout per omode) ----
    #pragma unroll
    for (int mt=0;mt<2;mt++){
        const int r0 = b0 + wM + mt*16 + g;
        #pragma unroll
        for (int nt=0;nt<4;nt++){
            const int oc = o0 + wN + nt*8 + t4*2;
            const float bv0 = bias[n*O_w + oc];
            const float bv1 = bias[n*O_w + oc + 1];
            float2 v0 = make_float2(acc[mt][nt][0]+bv0, acc[mt][nt][1]+bv1);
            float2 v1 = make_float2(acc[mt][nt][2]+bv0, acc[mt][nt][3]+bv1);
            long base0, base1;
            if (omode == 0){
                const int grp = oc >> 7, cc = oc & 127;
                const int cb = cc >> 5, c2 = cc & 31;
                const long inner = (long)n*128 + grp*32 + c2;
                base0 = ((long)(r0    )*4 + cb)*(NN*128) + inner;
                base1 = ((long)(r0 + 8)*4 + cb)*(NN*128) + inner;
            } else {
                base0 = ((long)(r0    )*NN + n)*O_w + oc;
                base1 = ((long)(r0 + 8)*NN + n)*O_w + oc;
            }
            *(float2*)&out[base0] = v0;
            *(float2*)&out[base1] = v1;
        }
    }
}

// ---------------------------------------------------------------------------
// G-mix + LSTM cell. grid (Bb, 4) x 128 threads.
// gates slice for (b, cb) is ONE contiguous 12 KB chunk now.
// ---------------------------------------------------------------------------
__global__ void __launch_bounds__(128) lstm_mix(
    const float* __restrict__ gates, const float* __restrict__ G,
    const float* __restrict__ c_in,  float* __restrict__ c_out,
    half* __restrict__ hH, half* __restrict__ hL,
    half* __restrict__ yiH, half* __restrict__ yiL)
{
    __shared__ float sGt[NN*128];   // [n*128 + grp*32 + cc]
    __shared__ float sGm[NN*NN];

    const int b = blockIdx.x, cb = blockIdx.y, c0 = cb*32;
    const int t = threadIdx.x;

    const float4* gb = (const float4*)(gates + ((long)b*4 + cb)*(NN*128));
    float4* s4w = (float4*)sGt;
    #pragma unroll
    for (int i=t; i<NN*32; i+=128) s4w[i] = gb[i];
    for (int i=t; i<NN*NN; i+=128) sGm[i] = G[i];
    __syncthreads();

    const int c = t & 31, mg = t >> 5;   // mg: 0..3, each 6 m
    float acc[6][4];
    #pragma unroll
    for (int mm=0;mm<6;mm++)
        #pragma unroll
        for (int j=0;j<4;j++) acc[mm][j]=0.f;

    #pragma unroll 4
    for (int n=0;n<NN;n++){
        float vi = sGt[n*128 +      c];
        float vf = sGt[n*128 + 32 + c];
        float vg = sGt[n*128 + 64 + c];
        float vo = sGt[n*128 + 96 + c];
        #pragma unroll
        for (int mm=0;mm<6;mm++){
            float gm = sGm[(mg*6+mm)*NN + n];
            acc[mm][0] = fmaf(gm, vi, acc[mm][0]);
            acc[mm][1] = fmaf(gm, vf, acc[mm][1]);
            acc[mm][2] = fmaf(gm, vg, acc[mm][2]);
            acc[mm][3] = fmaf(gm, vo, acc[mm][3]);
        }
    }
    #pragma unroll
    for (int mm=0;mm<6;mm++){
        const int m = mg*6+mm;
        const long idx = ((long)m*Bb + b)*128 + c0 + c;
        float cold = c_in[idx];
        float cn = sigf(acc[mm][1])*cold + sigf(acc[mm][0])*tanhacc(acc[mm][2]);
        float hn = sigf(acc[mm][3])*tanhacc(cn);
        c_out[idx] = cn;
        half h,l; splitH(hn, h, l);
        hH[idx]=h; hL[idx]=l;
        if (yiH){
            float y = tanhacc(hn);
            splitH(y, h, l);
            yiH[idx]=h; yiL[idx]=l;
        }
    }
}

// ---------------------------------------------------------------------------
// Head.  fcpre is b-major: block reads ONE contiguous 24.5 KB chunk.
// ---------------------------------------------------------------------------
__global__ void __launch_bounds__(256) head_kernel(
    const float* __restrict__ G,
    const float* __restrict__ locW, const float* __restrict__ locB,
    const float* __restrict__ lzW,  const float* __restrict__ lzB,
    float* __restrict__ out, int tstep)
{
    extern __shared__ float smem[];
    float* sP  = smem;                 // NN*256  [n*256 + f]
    float* sY  = sP  + NN*256;         // NN*256
    float* sG  = sY  + NN*256;         // NN*NN
    float* sQ  = sG  + NN*NN;          // NN*8
    float* sLW = sQ  + NN*8;           // 384
    float* sLZ = sLW + 128*3;          // 512

    const int b = blockIdx.x, t = threadIdx.x;
    {
        const float4* fp = (const float4*)(g_fcpre + (long)b*(NN*256));
        float4* s4w = (float4*)sP;
        #pragma unroll
        for (int i=t; i<NN*64; i+=256) s4w[i] = fp[i];
    }
    for (int i=t;i<NN*NN;i+=256)  sG[i]=G[i];
    for (int i=t;i<384;i+=256)    sLW[i]=locW[i];
    for (int i=t;i<512;i+=256)    sLZ[i]=lzW[i];
    __syncthreads();

    {
        const int ocg = t & 63;
        const int mg  = t >> 6;
        const float4* p4 = (const float4*)sP;
        float acc[6][4];
        #pragma unroll
        for (int mm=0;mm<6;mm++)
            #pragma unroll
            for (int j=0;j<4;j++) acc[mm][j]=0.f;
        #pragma unroll 4
        for (int n=0;n<NN;n++){
            float4 v = p4[n*64 + ocg];
            #pragma unroll
            for (int mm=0;mm<6;mm++){
                float gm = sG[(mg*6+mm)*NN + n];
                acc[mm][0]=fmaf(gm,v.x,acc[mm][0]); acc[mm][1]=fmaf(gm,v.y,acc[mm][1]);
                acc[mm][2]=fmaf(gm,v.z,acc[mm][2]); acc[mm][3]=fmaf(gm,v.w,acc[mm][3]);
            }
        }
        #pragma unroll
        for (int mm=0;mm<6;mm++){
            int m = mg*6+mm;
            *(float4*)&sY[m*256 + ocg*4] =
                make_float4(tanhacc(acc[mm][0]),tanhacc(acc[mm][1]),
                            tanhacc(acc[mm][2]),tanhacc(acc[mm][3]));
        }
    }
    __syncthreads();

    if (t < NN*7){
        int n = t/7, j = t%7;
        float a;
        if (j < 3){
            a = locB[j];
            #pragma unroll 8
            for (int f=0;f<128;f++) a = fmaf(sY[n*256+f], sLW[f*3+j], a);
        } else {
            int j2 = j-3;
            a = lzB[j2];
            #pragma unroll 8
            for (int f=0;f<128;f++) a = fmaf(sY[n*256+128+f], sLZ[f*4+j2], a);
        }
        sQ[n*8+j] = a;
    }
    __syncthreads();

    if (t < NN){
        int m = t;
        float s[7];
        #pragma unroll
        for (int j=0;j<7;j++){
            float a = 0.f;
            #pragma unroll 4
            for (int n=0;n<NN;n++) a = fmaf(sG[m*NN+n], sQ[n*8+j], a);
            s[j]=a;
        }
        float inv = rsqrtf(1.0f + s[0]*s[0] + s[1]*s[1] + s[2]*s[2]);
        float dw=inv, dx=s[0]*inv, dy=s[1]*inv, dz=s[2]*inv;
        long bm = (long)b*NN + m;
        float qw=g_locstart[bm*4+0], qx=g_locstart[bm*4+1],
              qy=g_locstart[bm*4+2], qz=g_locstart[bm*4+3];
        float lw = qw*dw - qx*dx - qy*dy - qz*dz;
        float lx = qw*dx + qx*dw + qy*dz - qz*dy;
        float ly = qw*dy - qx*dz + qy*dw + qz*dx;
        float lz = qw*dz + qx*dy - qy*dx + qz*dw;
        g_locstart[bm*4+0]=lw; g_locstart[bm*4+1]=lx;
        g_locstart[bm*4+2]=ly; g_locstart[bm*4+3]=lz;

        long oo = (((long)b*TT + tstep)*NN + m)*4;
        out[oo+0]=lw; out[oo+1]=lx; out[oo+2]=ly; out[oo+3]=lz;
        long oz = (long)Bb*TT*NN*4 + oo;
        out[oz+0]=s[3]; out[oz+1]=s[4]; out[oz+2]=s[5]; out[oz+3]=s[6];

        long xb = ((long)m*Bb + b)*96 + 64;
        float xv[8] = {lw,lx,ly,lz,dw,dx,dy,dz};
        #pragma unroll
        for (int j=0;j<8;j++){
            half h,l; splitH(xv[j], h, l);
            g_xiH[xb+j]=h; g_xiL[xb+j]=l;
        }
    }
}

// ---------------------------------------------------------------------------
// init_mix: h0/c0 = G @ y ; y b-major [(b*NN+n)*256]
// ---------------------------------------------------------------------------
__global__ void __launch_bounds__(256) init_mix(
    const float* __restrict__ y, const float* __restrict__ G)
{
    __shared__ float sY[NN*256];
    __shared__ float sG[NN*NN];
    const int b = blockIdx.x, t = threadIdx.x;
    {
        const float4* fp = (const float4*)(y + (long)b*(NN*256));
        float4* s4w = (float4*)sY;
        for (int i=t; i<NN*64; i+=256) s4w[i] = fp[i];
    }
    for (int i=t;i<NN*NN;i+=256) sG[i]=G[i];
    __syncthreads();
    for (int idx=t; idx<NN*128; idx+=256){
        int m = idx>>7, o = idx&127;
        float h0=0.f, c0=0.f;
        #pragma unroll 4
        for (int n=0;n<NN;n++){
            float gm = sG[m*NN+n];
            h0 = fmaf(gm, sY[n*256+o],     h0);
            c0 = fmaf(gm, sY[n*256+128+o], c0);
        }
        long off = ((long)m*Bb + b)*128 + o;
        g_c1[off]=c0; g_c2[off]=c0;
        half h,l; splitH(h0, h, l);
        g_h1H[off]=h; g_h1L[off]=l;
        g_h2H[off]=h; g_h2L[off]=l;
    }
}

// ---------------------------------------------------------------------------
// init_xi: xi halves (stride 96) + locstart + enc transpose
// ---------------------------------------------------------------------------
__global__ void init_xi(const float* __restrict__ x, const float* __restrict__ z,
                        const float* __restrict__ enc)
{
    int i = blockIdx.x*blockDim.x + threadIdx.x;
    if (i < NN*Bb*96){
        int f = i % 96, nb = i / 96;
        int b = nb % Bb, n = nb / Bb;
        float v = 0.f;
        if (f < 64)      v = z[(b*NN + n)*64 + f];
        else if (f < 72) v = x[(b*NN + n)*8 + (f-64)];
        half h,l; splitH(v, h, l);
        g_xiH[i]=h; g_xiL[i]=l;
    }
    if (i < Bb*NN*4){
        int j = i % 4, bn = i / 4;
        g_locstart[i] = x[bn*8 + j];
    }
    if (i < NN*Bb*256){
        int f = i % 256, nb = i / 256;
        int b = nb % Bb, n = nb / Bb;
        half h,l; splitH(enc[((long)b*NN + n)*256 + f], h, l);
        g_encH[i]=h; g_encL[i]=l;
    }
}

// ---------------------------------------------------------------------------
// fused prepack: 9 jobs by blockIdx.y
// ---------------------------------------------------------------------------
__global__ void prep_all(
    const float* __restrict__ Wx0, const float* __restrict__ Wh0,
    const float* __restrict__ Wx1, const float* __restrict__ Wh1,
    const float* __restrict__ fcW, const float* __restrict__ fc2W,
    const float* __restrict__ fcB, const float* __restrict__ fc2B,
    const float* __restrict__ ih1W, const float* __restrict__ ih2W,
    const float* __restrict__ ih1B, const float* __restrict__ ih2B)
{
    const int job = blockIdx.y;
    if (job == 6){
        for (int i = blockIdx.x*blockDim.x + threadIdx.x; i < NN*256;
             i += gridDim.x*blockDim.x){
            int n = i >> 8, j = i & 255;
            g_fcBc[i] = (j < 128) ? fcB[n*128 + j] : fc2B[n*128 + (j-128)];
            g_ihBc[i] = (j < 128) ? ih1B[j] : ih2B[j-128];
        }
        return;
    }
    if (job >= 7){
        const float* src = (job == 7) ? ih1W : ih2W;
        const int colOff = (job == 7) ? 0 : 128;
        for (int i = blockIdx.x*blockDim.x + threadIdx.x; i < 256*128;
             i += gridDim.x*blockDim.x){
            int r = i >> 7, o = i & 127;
            half h,l; splitH(src[r*128 + o], h, l);
            int di = r*256 + colOff + o;
            g_wiH[di]=h; g_wiL[di]=l;
        }
        return;
    }
    const float* src; half *dH, *dL;
    int Ksrc, Osrc, Kdst, Odst, rowOff, colOff, rows;
    switch(job){
        case 0: src=Wx0; dH=g_w0H; dL=g_w0L; Ksrc=72;  Osrc=512; Kdst=224; Odst=512; rowOff=0;   colOff=0;   rows=96;  break;
        case 1: src=Wh0; dH=g_w0H; dL=g_w0L; Ksrc=128; Osrc=512; Kdst=224; Odst=512; rowOff=96;  colOff=0;   rows=128; break;
        case 2: src=Wx1; dH=g_w1H; dL=g_w1L; Ksrc=128; Osrc=512; Kdst=256; Odst=512; rowOff=0;   colOff=0;   rows=128; break;
        case 3: src=Wh1; dH=g_w1H; dL=g_w1L; Ksrc=128; Osrc=512; Kdst=256; Odst=512; rowOff=128; colOff=0;   rows=128; break;
        case 4: src=fcW; dH=g_wfH; dL=g_wfL; Ksrc=128; Osrc=128; Kdst=128; Odst=256; rowOff=0;   colOff=0;   rows=128; break;
        default:src=fc2W;dH=g_wfH; dL=g_wfL; Ksrc=128; Osrc=128; Kdst=128; Odst=256; rowOff=0;   colOff=128; rows=128; break;
    }
    long total = (long)NN*rows*Osrc;
    for (long idx = blockIdx.x*blockDim.x + threadIdx.x; idx < total;
         idx += (long)gridDim.x*blockDim.x){
        int o = idx % Osrc;
        int r = (idx / Osrc) % rows;
        int n = idx / ((long)Osrc*rows);
        float v = (r < Ksrc) ? src[((long)n*Ksrc + r)*Osrc + o] : 0.f;
        half h,l; splitH(v, h, l);
        long di = ((long)n*Kdst + rowOff + r)*Odst + colOff + o;
        dH[di]=h; dL[di]=l;
    }
}

// ---------------------------------------------------------------------------
extern "C" void kernel_launch(void* const* d_in, const int* in_sizes, int n_in,
                              void* d_out, int out_size)
{
    const float* x    = (const float*)d_in[0];
    const float* enc  = (const float*)d_in[1];
    const float* z    = (const float*)d_in[2];
    const float* G    = (const float*)d_in[4];
    const float* Wx0  = (const float*)d_in[5];
    const float* Wh0  = (const float*)d_in[6];
    const float* b0_  = (const float*)d_in[7];
    const float* Wx1  = (const float*)d_in[8];
    const float* Wh1  = (const float*)d_in[9];
    const float* b1_  = (const float*)d_in[10];
    const float* fcW  = (const float*)d_in[11];
    const float* fcB  = (const float*)d_in[12];
    const float* fc2W = (const float*)d_in[13];
    const float* fc2B = (const float*)d_in[14];
    const float* ih1W = (const float*)d_in[15];
    const float* ih1B = (const float*)d_in[16];
    const float* ih2W = (const float*)d_in[17];
    const float* ih2B = (const float*)d_in[18];
    const float* locW = (const float*)d_in[19];
    const float* locB = (const float*)d_in[20];
    const float* lzW  = (const float*)d_in[21];
    const float* lzB  = (const float*)d_in[22];
    float* out = (float*)d_out;

    half *xiH,*xiL,*h1H,*h1L,*h2H,*h2L,*yiH,*yiL,*encH,*encL;
    half *w0H,*w0L,*w1H,*w1L,*wfH,*wfL,*wiH,*wiL;
    float *c1,*c2,*gates,*fcpre,*fcBc,*ihBc;
    cudaGetSymbolAddress((void**)&xiH, g_xiH); cudaGetSymbolAddress((void**)&xiL, g_xiL);
    cudaGetSymbolAddress((void**)&h1H, g_h1H); cudaGetSymbolAddress((void**)&h1L, g_h1L);
    cudaGetSymbolAddress((void**)&h2H, g_h2H); cudaGetSymbolAddress((void**)&h2L, g_h2L);
    cudaGetSymbolAddress((void**)&yiH, g_yiH); cudaGetSymbolAddress((void**)&yiL, g_yiL);
    cudaGetSymbolAddress((void**)&encH, g_encH); cudaGetSymbolAddress((void**)&encL, g_encL);
    cudaGetSymbolAddress((void**)&w0H, g_w0H); cudaGetSymbolAddress((void**)&w0L, g_w0L);
    cudaGetSymbolAddress((void**)&w1H, g_w1H); cudaGetSymbolAddress((void**)&w1L, g_w1L);
    cudaGetSymbolAddress((void**)&wfH, g_wfH); cudaGetSymbolAddress((void**)&wfL, g_wfL);
    cudaGetSymbolAddress((void**)&wiH, g_wiH); cudaGetSymbolAddress((void**)&wiL, g_wiL);
    cudaGetSymbolAddress((void**)&c1, g_c1);   cudaGetSymbolAddress((void**)&c2, g_c2);
    cudaGetSymbolAddress((void**)&gates, g_gates);
    cudaGetSymbolAddress((void**)&fcpre, g_fcpre);
    cudaGetSymbolAddress((void**)&fcBc, g_fcBc);
    cudaGetSymbolAddress((void**)&ihBc, g_ihBc);

    const int smem_head = (NN*256 + NN*256 + NN*NN + NN*8 + 128*3 + 128*4)*4;
    cudaFuncSetAttribute(head_kernel,cudaFuncAttributeMaxDynamicSharedMemorySize, smem_head);

    // ---- setup ----
    prep_all<<<dim3(256,9), 256>>>(Wx0, Wh0, Wx1, Wh1, fcW, fc2W, fcB, fc2B,
                                   ih1W, ih2W, ih1B, ih2B);
    init_xi<<<(NN*Bb*256 + 255)/256, 256>>>(x, z, enc);
    // y = enc @ [ih1W|ih2W] + [ih1b|ih2b]  (shared weights Kw=0; b-major out)
    gemm_fp16<<<dim3(NN,2,8), 256>>>(encH, encL, 8, 256,
                                     (half*)nullptr, (half*)nullptr, 0, 0,
                                     wiH, wiL, 0, ihBc, 256, 1, fcpre);
    init_mix<<<Bb, 256>>>(fcpre, G);

    dim3 gl(NN, 4, Bb/64);   // lstm gemms: O=512 (gates layout)
    dim3 gf(NN, 2, Bb/64);   // fc gemm:   O=256 (b-major)
    dim3 gm(Bb, 4);          // lstm_mix

    for (int t = 0; t < TT; t++){
        gemm_fp16<<<gl, 256>>>(xiH, xiL, 3, 96,  h1H, h1L, 4, 128,
                               w0H, w0L, 224, b0_, 512, 0, gates);
        lstm_mix <<<gm, 128>>>(gates, G, c1, c1, h1H, h1L, nullptr, nullptr);
        gemm_fp16<<<gl, 256>>>(h1H, h1L, 4, 128, h2H, h2L, 4, 128,
                               w1H, w1L, 256, b1_, 512, 0, gates);
        lstm_mix <<<gm, 128>>>(gates, G, c2, c2, h2H, h2L, yiH, yiL);
        gemm_fp16<<<gf, 256>>>(yiH, yiL, 4, 128, (half*)nullptr, (half*)nullptr, 0, 0,
                               wfH, wfL, 128, fcBc, 256, 1, fcpre);
        head_kernel<<<Bb, 256, smem_head>>>(G, locW, locB, lzW, lzB, out, t);
    }
}